// round 16
// baseline (speedup 1.0000x reference)
#include <cuda_runtime.h>
#include <cstdint>

#define BATCH 8192
#define NH    16
#define HD    256
#define FH    512

// ---------------- scratch (static device arrays; no allocations) ------------
__device__ float    g_p[(size_t)NH * BATCH * HD];     // residual, head-major, fp32
__device__ uint16_t g_h[(size_t)NH * BATCH * HD];     // rmsnorm2 out, fp16
__device__ uint16_t g_gate[(size_t)NH * BATCH * FH];  // silu(h@w1)*(h@w3), fp16
__device__ uint16_t g_w1t[(size_t)NH * FH * HD];      // w1^T fp16 [h][n=512][k=256]
__device__ uint16_t g_w3t[(size_t)NH * FH * HD];
__device__ uint16_t g_w2t[(size_t)NH * HD * FH];      // w2^T fp16 [h][n=256][k=512]

// ---------------- PTX helpers -----------------------------------------------
__device__ __forceinline__ uint32_t smem_u32(const void* p) {
    uint32_t a;
    asm("{ .reg .u64 t; cvta.to.shared.u64 t, %1; cvt.u32.u64 %0, t; }" : "=r"(a) : "l"(p));
    return a;
}
__device__ __forceinline__ uint16_t f2h(float x) {
    uint16_t r;
    asm("cvt.rn.f16.f32 %0, %1;" : "=h"(r) : "f"(x));
    return r;
}
__device__ __forceinline__ uint32_t f2h2(float lo, float hi) {
    uint32_t r;   // packed {lo, hi}
    asm("cvt.rn.f16x2.f32 %0, %1, %2;" : "=r"(r) : "f"(hi), "f"(lo));
    return r;
}
__device__ __forceinline__ void cp16(uint32_t d, const void* s) {
    asm volatile("cp.async.cg.shared.global [%0], [%1], 16;" :: "r"(d), "l"(s));
}
__device__ __forceinline__ void cp_commit() {
    asm volatile("cp.async.commit_group;" ::: "memory");
}
template<int N> __device__ __forceinline__ void cp_wait() {
    asm volatile("cp.async.wait_group %0;" :: "n"(N) : "memory");
}
__device__ __forceinline__ void ldsm4(uint32_t* r, uint32_t a) {
    asm volatile("ldmatrix.sync.aligned.m8n8.x4.shared.b16 {%0,%1,%2,%3}, [%4];"
                 : "=r"(r[0]), "=r"(r[1]), "=r"(r[2]), "=r"(r[3]) : "r"(a));
}
// D(16x8) += A(16x16,f16) * B(16x8,f16)^T, fp32 accum
__device__ __forceinline__ void mma16(float* c, const uint32_t* a, uint32_t b0, uint32_t b1) {
    asm volatile(
        "mma.sync.aligned.m16n8k16.row.col.f32.f16.f16.f32 "
        "{%0,%1,%2,%3}, {%4,%5,%6,%7}, {%8,%9}, {%0,%1,%2,%3};"
        : "+f"(c[0]), "+f"(c[1]), "+f"(c[2]), "+f"(c[3])
        : "r"(a[0]), "r"(a[1]), "r"(a[2]), "r"(a[3]), "r"(b0), "r"(b1));
}

// ---------------- kernel 0: weight transposes + fp16 conversion -------------
__global__ __launch_bounds__(256) void transpose_kernel(
    const float* __restrict__ w1, const float* __restrict__ w3,
    const float* __restrict__ w2)
{
    __shared__ float s[32][33];
    const int zz = blockIdx.z;
    const int tensor = zz >> 4, head = zz & 15;
    const float* src;
    uint16_t* dst;
    int R, C;
    if (tensor == 0)      { src = w1 + (size_t)head * HD * FH; dst = g_w1t + (size_t)head * FH * HD; R = HD; C = FH; }
    else if (tensor == 1) { src = w3 + (size_t)head * HD * FH; dst = g_w3t + (size_t)head * FH * HD; R = HD; C = FH; }
    else                  { src = w2 + (size_t)head * FH * HD; dst = g_w2t + (size_t)head * HD * FH; R = FH; C = HD; }

    const int r0 = blockIdx.y * 32, c0 = blockIdx.x * 32;
    if (r0 >= R || c0 >= C) return;
    const int tx = threadIdx.x & 31, ty = threadIdx.x >> 5;
#pragma unroll
    for (int j = 0; j < 4; j++)
        s[ty + 8 * j][tx] = src[(size_t)(r0 + ty + 8 * j) * C + c0 + tx];
    __syncthreads();
#pragma unroll
    for (int j = 0; j < 4; j++)
        dst[(size_t)(c0 + ty + 8 * j) * R + r0 + tx] = f2h(s[tx][ty + 8 * j]);
}

// ---------------- kernel 1: rmsnorm1 -> headmix*mask + x -> rmsnorm2 --------
__global__ __launch_bounds__(512) void mix_kernel(
    const float* __restrict__ x,
    const float* __restrict__ n1w,
    const float* __restrict__ n2w,
    const float* __restrict__ mask)
{
    __shared__ float xn[16 * 272];

    const int b    = blockIdx.x;
    const int w    = threadIdx.x >> 5;
    const int lane = threadIdx.x & 31;

    const float* xb = x + ((size_t)b * NH + w) * HD;

    float2 v[4];
    float ss = 0.f;
#pragma unroll
    for (int q = 0; q < 4; q++) {
        int d = 2 * lane + 64 * q;
        v[q] = *(const float2*)(xb + d);
        ss += v[q].x * v[q].x + v[q].y * v[q].y;
    }
#pragma unroll
    for (int o = 16; o > 0; o >>= 1) ss += __shfl_xor_sync(0xffffffffu, ss, o);
    float rms = rsqrtf(ss * (1.f / HD) + 1e-6f);
#pragma unroll
    for (int q = 0; q < 4; q++) {
        int d = 2 * lane + 64 * q;
        float2 nw = *(const float2*)(n1w + d);
        float2 xv = make_float2(v[q].x * rms * nw.x, v[q].y * rms * nw.y);
        *(float2*)&xn[w * 272 + d] = xv;
    }
    __syncthreads();

    float2 p[4];
    float ps = 0.f;
#pragma unroll
    for (int q = 0; q < 4; q++) {
        int d = 2 * lane + 64 * q;
        int j = d >> 4;
        int t = d & 15;
        float2 xm = *(const float2*)&xn[j * 272 + (w << 4) + t];
        float2 mk = *(const float2*)(mask + w * HD + d);
        float p0 = xm.x * mk.x + v[q].x;
        float p1 = xm.y * mk.y + v[q].y;
        p[q] = make_float2(p0, p1);
        ps += p0 * p0 + p1 * p1;
    }
#pragma unroll
    for (int o = 16; o > 0; o >>= 1) ps += __shfl_xor_sync(0xffffffffu, ps, o);
    float rms2 = rsqrtf(ps * (1.f / HD) + 1e-6f);

    const size_t base = ((size_t)w * BATCH + b) * HD;   // head-major
#pragma unroll
    for (int q = 0; q < 4; q++) {
        int d = 2 * lane + 64 * q;
        *(float2*)(g_p + base + d) = p[q];
        float2 nw = *(const float2*)(n2w + d);
        *(uint32_t*)(g_h + base + d) =
            f2h2(p[q].x * rms2 * nw.x, p[q].y * rms2 * nw.y);
    }
}

// ---------------- kernel 2: fused  g_gate = fp16(silu(H@W1) * (H@W3)) -------
// Resident-A variant: full A tile (128 x 256 fp16 = 64KB) loaded once; B1/B3
// streamed 3-stage (16KB/stage) over 4 n-blocks of 64 cols each.
// warps 2(M) x 4(N); warp tile 64x16 per matrix, shared A fragment.
// smem = 64KB A + 48KB B = 112KB; 2 CTAs/SM.
__global__ __launch_bounds__(256, 2) void ffn1_kernel()
{
    constexpr int ITERS = 16;            // 4 n-blocks x 4 k-tiles
    extern __shared__ char smem[];
    const uint32_t sbase = smem_u32(smem);
    const uint32_t bbase = sbase + 65536u;

    const int head  = blockIdx.z;
    const int b0    = blockIdx.x * 128;
    const int nbase = blockIdx.y * 256;
    const int tid   = threadIdx.x;

    const uint16_t* Ag  = g_h   + ((size_t)head * BATCH + b0) * HD;
    const uint16_t* B1g = g_w1t + ((size_t)head * FH + nbase) * HD;
    const uint16_t* B3g = g_w3t + ((size_t)head * FH + nbase) * HD;

    // B loader: 2 rows per thread per matrix (64 rows x 8 chunks of 16B)
    const int brow = tid >> 3;           // 0..31
    const int lq   = tid & 7;
    uint32_t bdst[2];
    const uint16_t* b1src[2];
    const uint16_t* b3src[2];
#pragma unroll
    for (int t = 0; t < 2; t++) {
        int r = brow + 32 * t;           // 0..63
        bdst[t] = (uint32_t)r * 128 + ((uint32_t)(lq ^ (r & 7)) << 4);
        b1src[t] = B1g + (size_t)r * HD + lq * 8;
        b3src[t] = B3g + (size_t)r * HD + lq * 8;
    }

    auto load_B = [&](int it, int buf) {
        const int nb = it >> 2, kt = it & 3;
        const size_t off = (size_t)nb * 64 * HD + (size_t)kt * 64;
        uint32_t s = bbase + (uint32_t)buf * 16384u;
#pragma unroll
        for (int t = 0; t < 2; t++) cp16(s + bdst[t], b1src[t] + off);
#pragma unroll
        for (int t = 0; t < 2; t++) cp16(s + 8192u + bdst[t], b3src[t] + off);
    };

    // group 0: full A tile (4 k-chunks of 128 rows x 128B, swizzled) + B(it=0)
#pragma unroll
    for (int t = 0; t < 16; t++) {
        int i   = tid + 256 * t;
        int kc  = i >> 10;               // 0..3
        int rem = i & 1023;
        int r   = rem >> 3;              // 0..127
        int q   = rem & 7;
        cp16(sbase + (uint32_t)kc * 16384u + (uint32_t)r * 128u
                   + ((uint32_t)(q ^ (r & 7)) << 4),
             Ag + (size_t)r * HD + (size_t)kc * 64 + q * 8);
    }
    load_B(0, 0);
    cp_commit();
    load_B(1, 1); cp_commit();

    // compute mapping (m16n8k16 fragments)
    const int lane = tid & 31, warp = tid >> 5;
    const int wm = warp & 1, wn = warp >> 1;         // 2 x 4
    uint32_t aoff[4], boff;
    {
        int rb = wm * 64 + (lane & 7) + 8 * ((lane >> 3) & 1);
        int c  = lane >> 4;
#pragma unroll
        for (int mi = 0; mi < 4; mi++) {
            int m = rb + 16 * mi;
            aoff[mi] = (uint32_t)m * 128 + ((uint32_t)(c ^ (m & 7)) << 4);
        }
        int n = wn * 16 + (lane & 7) + 8 * ((lane >> 3) & 1);
        boff = (uint32_t)n * 128 + ((uint32_t)(c ^ (n & 7)) << 4);
    }

    float acc1[8][4], acc3[8][4];
#pragma unroll
    for (int i = 0; i < 8; i++)
#pragma unroll
        for (int j = 0; j < 4; j++) { acc1[i][j] = 0.f; acc3[i][j] = 0.f; }

    const int g  = lane >> 2, tg = lane & 3;

    for (int it = 0; it < ITERS; it++) {
        if (it == ITERS - 1) cp_wait<0>(); else cp_wait<1>();
        __syncthreads();
        if (it + 2 < ITERS) { load_B(it + 2, (it + 2) % 3); cp_commit(); }

        const int kt = it & 3;
        uint32_t sA  = sbase + (uint32_t)kt * 16384u;
        uint32_t sB1 = bbase + (uint32_t)(it % 3) * 16384u;
        uint32_t sB3 = sB1 + 8192u;
#pragma unroll
        for (int j = 0; j < 4; j++) {            // k16 steps within k64 tile
            uint32_t xo = (uint32_t)j << 5;
            uint32_t a[4][4], b1[4], b3[4];
#pragma unroll
            for (int mi = 0; mi < 4; mi++) ldsm4(a[mi], sA + (aoff[mi] ^ xo));
            ldsm4(b1, sB1 + (boff ^ xo));
            ldsm4(b3, sB3 + (boff ^ xo));
#pragma unroll
            for (int mi = 0; mi < 4; mi++)
#pragma unroll
                for (int nj = 0; nj < 2; nj++) {
                    mma16(acc1[mi * 2 + nj], a[mi], b1[nj], b1[nj + 2]);
                    mma16(acc3[mi * 2 + nj], a[mi], b3[nj], b3[nj + 2]);
                }
        }

        if (kt == 3) {
            // epilogue for n-block nb = it>>2, then reset accumulators
            const int nb = it >> 2;
            uint16_t* c = g_gate + ((size_t)head * BATCH + b0) * FH
                        + nbase + nb * 64;
#pragma unroll
            for (int mi = 0; mi < 4; mi++) {
#pragma unroll
                for (int nj = 0; nj < 2; nj++) {
                    float* d1 = acc1[mi * 2 + nj];
                    float* d3 = acc3[mi * 2 + nj];
                    int row = wm * 64 + mi * 16 + g;
                    int col = wn * 16 + nj * 8 + 2 * tg;
#pragma unroll
                    for (int h = 0; h < 2; h++) {
                        float a0 = d1[2 * h], a1 = d1[2 * h + 1];
                        float g0 = a0 / (1.f + __expf(-a0)) * d3[2 * h];
                        float g1 = a1 / (1.f + __expf(-a1)) * d3[2 * h + 1];
                        *(uint32_t*)(c + (size_t)(row + 8 * h) * FH + col) =
                            f2h2(g0, g1);
                    }
                }
            }
#pragma unroll
            for (int i = 0; i < 8; i++)
#pragma unroll
                for (int j = 0; j < 4; j++) { acc1[i][j] = 0.f; acc3[i][j] = 0.f; }
        }
    }
}

// ---------------- kernel 3: out = G @ W2 + P (token-major out) --------------
// fp16 path. CTA: 128x128, K=512, k-tile 64. warps 2(M) x 4(N); warp tile 64x32.
__global__ __launch_bounds__(256, 2) void ffn2_kernel(float* __restrict__ outp)
{
    constexpr int KT = FH / 64;   // 8
    extern __shared__ char smem[];
    const uint32_t sbase = smem_u32(smem);

    const int head = blockIdx.z;
    const int b0 = blockIdx.x * 128;
    const int n0 = blockIdx.y * 128;
    const int tid = threadIdx.x;

    const uint16_t* Ag = g_gate + ((size_t)head * BATCH + b0) * FH;
    const uint16_t* Bg = g_w2t  + ((size_t)head * HD + n0) * FH;

    const int lrow = tid >> 3;
    const int lq   = tid & 7;
    uint32_t adst[4];
    const uint16_t* asrc[4];
    const uint16_t* bsrc[4];
#pragma unroll
    for (int t = 0; t < 4; t++) {
        int r = lrow + 32 * t;          // 0..127 (A rows and B rows both 128)
        adst[t] = (uint32_t)r * 128 + ((uint32_t)(lq ^ (r & 7)) << 4);
        asrc[t] = Ag + (size_t)r * FH + lq * 8;
        bsrc[t] = Bg + (size_t)r * FH + lq * 8;
    }

    const int lane = tid & 31, warp = tid >> 5;
    const int wm = warp & 1, wn = warp >> 1;
    uint32_t aoff[4], boff[2];
    {
        int rb = wm * 64 + (lane & 7) + 8 * ((lane >> 3) & 1);
        int c  = lane >> 4;
#pragma unroll
        for (int mi = 0; mi < 4; mi++) {
            int m = rb + 16 * mi;
            aoff[mi] = (uint32_t)m * 128 + ((uint32_t)(c ^ (m & 7)) << 4);
        }
#pragma unroll
        for (int p = 0; p < 2; p++) {
            int n = wn * 32 + p * 16 + (lane & 7) + 8 * ((lane >> 3) & 1);
            boff[p] = (uint32_t)n * 128 + ((uint32_t)(c ^ (n & 7)) << 4);
        }
    }

    float acc[16][4];
#pragma unroll
    for (int i = 0; i < 16; i++)
#pragma unroll
        for (int j = 0; j < 4; j++) acc[i][j] = 0.f;

    auto load_tile = [&](int kt, int buf) {
        uint32_t s = sbase + buf * 32768u;
#pragma unroll
        for (int t = 0; t < 4; t++) cp16(s + adst[t], asrc[t] + kt * 64);
#pragma unroll
        for (int t = 0; t < 4; t++) cp16(s + 16384u + adst[t], bsrc[t] + kt * 64);
    };

    load_tile(0, 0); cp_commit();
    load_tile(1, 1); cp_commit();

    for (int kt = 0; kt < KT; kt++) {
        if (kt == KT - 1) cp_wait<0>(); else cp_wait<1>();
        __syncthreads();
        if (kt + 2 < KT) { load_tile(kt + 2, (kt + 2) % 3); cp_commit(); }

        uint32_t sA = sbase + (uint32_t)(kt % 3) * 32768u;
        uint32_t sB = sA + 16384u;
#pragma unroll
        for (int j = 0; j < 4; j++) {
            uint32_t xo = (uint32_t)j << 5;
            uint32_t a[4][4], b[2][4];
#pragma unroll
            for (int mi = 0; mi < 4; mi++) ldsm4(a[mi], sA + (aoff[mi] ^ xo));
#pragma unroll
            for (int p = 0; p < 2; p++) ldsm4(b[p], sB + (boff[p] ^ xo));
#pragma unroll
            for (int mi = 0; mi < 4; mi++)
#pragma unroll
                for (int nj = 0; nj < 4; nj++)
                    mma16(acc[mi * 4 + nj], a[mi],
                          b[nj >> 1][nj & 1], b[nj >> 1][(nj & 1) + 2]);
        }
    }

    const int g = lane >> 2, tg = lane & 3;
    const float* px = g_p + ((size_t)head * BATCH + b0) * HD + n0;
#pragma unroll
    for (int mi = 0; mi < 4; mi++) {
#pragma unroll
        for (int nj = 0; nj < 4; nj++) {
            float* d = acc[mi * 4 + nj];
            int row = wm * 64 + mi * 16 + g;
            int col = wn * 32 + nj * 8 + 2 * tg;
#pragma unroll
            for (int h = 0; h < 2; h++) {
                float2 pv = *(const float2*)(px + (size_t)(row + 8 * h) * HD + col);
                float2 o = make_float2(d[2 * h] + pv.x, d[2 * h + 1] + pv.y);
                *(float2*)(outp + (size_t)(b0 + row + 8 * h) * NH * HD
                                + (size_t)head * HD + n0 + col) = o;
            }
        }
    }
}

// ---------------- launcher --------------------------------------------------
extern "C" void kernel_launch(void* const* d_in, const int* in_sizes, int n_in,
                              void* d_out, int out_size)
{
    const float* x    = (const float*)d_in[0];
    const float* n1w  = (const float*)d_in[1];
    const float* n2w  = (const float*)d_in[2];
    const float* w1   = (const float*)d_in[3];
    const float* w3   = (const float*)d_in[4];
    const float* w2   = (const float*)d_in[5];
    const float* mask = (const float*)d_in[6];
    float* out = (float*)d_out;

    cudaFuncSetAttribute(ffn1_kernel, cudaFuncAttributeMaxDynamicSharedMemorySize, 114688);
    cudaFuncSetAttribute(ffn2_kernel, cudaFuncAttributeMaxDynamicSharedMemorySize, 98304);

    transpose_kernel<<<dim3(16, 16, 48), 256>>>(w1, w3, w2);
    mix_kernel<<<BATCH, 512>>>(x, n1w, n2w, mask);
    ffn1_kernel<<<dim3(BATCH / 128, FH / 256, NH), 256, 114688>>>();
    ffn2_kernel<<<dim3(BATCH / 128, HD / 128, NH), 256, 98304>>>(out);
}

// round 17
// speedup vs baseline: 1.1175x; 1.1175x over previous
#include <cuda_runtime.h>
#include <cuda_fp16.h>
#include <cstdint>

#define BATCH 8192
#define NH    16
#define HD    256
#define FH    512

// ---------------- scratch (static device arrays; no allocations) ------------
__device__ uint16_t g_p[(size_t)NH * BATCH * HD];     // residual, head-major, fp16
__device__ uint16_t g_h[(size_t)NH * BATCH * HD];     // rmsnorm2 out, fp16
__device__ uint16_t g_gate[(size_t)NH * BATCH * FH];  // silu(h@w1)*(h@w3), fp16
__device__ uint16_t g_w1t[(size_t)NH * FH * HD];      // w1^T fp16 [h][n=512][k=256]
__device__ uint16_t g_w3t[(size_t)NH * FH * HD];
__device__ uint16_t g_w2t[(size_t)NH * HD * FH];      // w2^T fp16 [h][n=256][k=512]

// ---------------- PTX helpers -----------------------------------------------
__device__ __forceinline__ uint32_t smem_u32(const void* p) {
    uint32_t a;
    asm("{ .reg .u64 t; cvta.to.shared.u64 t, %1; cvt.u32.u64 %0, t; }" : "=r"(a) : "l"(p));
    return a;
}
__device__ __forceinline__ uint16_t f2h(float x) {
    uint16_t r;
    asm("cvt.rn.f16.f32 %0, %1;" : "=h"(r) : "f"(x));
    return r;
}
__device__ __forceinline__ uint32_t f2h2(float lo, float hi) {
    uint32_t r;   // packed {lo, hi}
    asm("cvt.rn.f16x2.f32 %0, %1, %2;" : "=r"(r) : "f"(hi), "f"(lo));
    return r;
}
__device__ __forceinline__ void cp16(uint32_t d, const void* s) {
    asm volatile("cp.async.cg.shared.global [%0], [%1], 16;" :: "r"(d), "l"(s));
}
__device__ __forceinline__ void cp_commit() {
    asm volatile("cp.async.commit_group;" ::: "memory");
}
template<int N> __device__ __forceinline__ void cp_wait() {
    asm volatile("cp.async.wait_group %0;" :: "n"(N) : "memory");
}
__device__ __forceinline__ void ldsm4(uint32_t* r, uint32_t a) {
    asm volatile("ldmatrix.sync.aligned.m8n8.x4.shared.b16 {%0,%1,%2,%3}, [%4];"
                 : "=r"(r[0]), "=r"(r[1]), "=r"(r[2]), "=r"(r[3]) : "r"(a));
}
// D(16x8) += A(16x16,f16) * B(16x8,f16)^T, fp32 accum
__device__ __forceinline__ void mma16(float* c, const uint32_t* a, uint32_t b0, uint32_t b1) {
    asm volatile(
        "mma.sync.aligned.m16n8k16.row.col.f32.f16.f16.f32 "
        "{%0,%1,%2,%3}, {%4,%5,%6,%7}, {%8,%9}, {%0,%1,%2,%3};"
        : "+f"(c[0]), "+f"(c[1]), "+f"(c[2]), "+f"(c[3])
        : "r"(a[0]), "r"(a[1]), "r"(a[2]), "r"(a[3]), "r"(b0), "r"(b1));
}

// ---------------- kernel 0: weight transposes + fp16 conversion -------------
__global__ __launch_bounds__(256) void transpose_kernel(
    const float* __restrict__ w1, const float* __restrict__ w3,
    const float* __restrict__ w2)
{
    __shared__ float s[32][33];
    const int zz = blockIdx.z;
    const int tensor = zz >> 4, head = zz & 15;
    const float* src;
    uint16_t* dst;
    int R, C;
    if (tensor == 0)      { src = w1 + (size_t)head * HD * FH; dst = g_w1t + (size_t)head * FH * HD; R = HD; C = FH; }
    else if (tensor == 1) { src = w3 + (size_t)head * HD * FH; dst = g_w3t + (size_t)head * FH * HD; R = HD; C = FH; }
    else                  { src = w2 + (size_t)head * FH * HD; dst = g_w2t + (size_t)head * HD * FH; R = FH; C = HD; }

    const int r0 = blockIdx.y * 32, c0 = blockIdx.x * 32;
    if (r0 >= R || c0 >= C) return;
    const int tx = threadIdx.x & 31, ty = threadIdx.x >> 5;
#pragma unroll
    for (int j = 0; j < 4; j++)
        s[ty + 8 * j][tx] = src[(size_t)(r0 + ty + 8 * j) * C + c0 + tx];
    __syncthreads();
#pragma unroll
    for (int j = 0; j < 4; j++)
        dst[(size_t)(c0 + ty + 8 * j) * R + r0 + tx] = f2h(s[tx][ty + 8 * j]);
}

// ---------------- kernel 1: rmsnorm1 -> headmix*mask + x -> rmsnorm2 --------
__global__ __launch_bounds__(512) void mix_kernel(
    const float* __restrict__ x,
    const float* __restrict__ n1w,
    const float* __restrict__ n2w,
    const float* __restrict__ mask)
{
    __shared__ float xn[16 * 272];

    const int b    = blockIdx.x;
    const int w    = threadIdx.x >> 5;
    const int lane = threadIdx.x & 31;

    const float* xb = x + ((size_t)b * NH + w) * HD;

    float2 v[4];
    float ss = 0.f;
#pragma unroll
    for (int q = 0; q < 4; q++) {
        int d = 2 * lane + 64 * q;
        v[q] = *(const float2*)(xb + d);
        ss += v[q].x * v[q].x + v[q].y * v[q].y;
    }
#pragma unroll
    for (int o = 16; o > 0; o >>= 1) ss += __shfl_xor_sync(0xffffffffu, ss, o);
    float rms = rsqrtf(ss * (1.f / HD) + 1e-6f);
#pragma unroll
    for (int q = 0; q < 4; q++) {
        int d = 2 * lane + 64 * q;
        float2 nw = *(const float2*)(n1w + d);
        float2 xv = make_float2(v[q].x * rms * nw.x, v[q].y * rms * nw.y);
        *(float2*)&xn[w * 272 + d] = xv;
    }
    __syncthreads();

    float2 p[4];
    float ps = 0.f;
#pragma unroll
    for (int q = 0; q < 4; q++) {
        int d = 2 * lane + 64 * q;
        int j = d >> 4;
        int t = d & 15;
        float2 xm = *(const float2*)&xn[j * 272 + (w << 4) + t];
        float2 mk = *(const float2*)(mask + w * HD + d);
        float p0 = xm.x * mk.x + v[q].x;
        float p1 = xm.y * mk.y + v[q].y;
        p[q] = make_float2(p0, p1);
        ps += p0 * p0 + p1 * p1;
    }
#pragma unroll
    for (int o = 16; o > 0; o >>= 1) ps += __shfl_xor_sync(0xffffffffu, ps, o);
    float rms2 = rsqrtf(ps * (1.f / HD) + 1e-6f);

    const size_t base = ((size_t)w * BATCH + b) * HD;   // head-major
#pragma unroll
    for (int q = 0; q < 4; q++) {
        int d = 2 * lane + 64 * q;
        *(uint32_t*)(g_p + base + d) = f2h2(p[q].x, p[q].y);
        float2 nw = *(const float2*)(n2w + d);
        *(uint32_t*)(g_h + base + d) =
            f2h2(p[q].x * rms2 * nw.x, p[q].y * rms2 * nw.y);
    }
}

// ---------------- kernel 2: fused  g_gate = fp16(silu(H@W1) * (H@W3)) -------
// fp16 path. CTA: M=128, N=64 (per matrix). warps 2(M) x 4(N); warp tile 64x16
// per matrix, shared A frag. k-tile = 64 elems (128B rows). 3-stage x 32KB.
__global__ __launch_bounds__(256, 2) void ffn1_kernel()
{
    constexpr int KT = HD / 64;   // 4
    extern __shared__ char smem[];
    const uint32_t sbase = smem_u32(smem);

    const int head = blockIdx.z;
    const int b0 = blockIdx.x * 128;
    const int n0 = blockIdx.y * 64;
    const int tid = threadIdx.x;

    const uint16_t* Ag  = g_h   + ((size_t)head * BATCH + b0) * HD;
    const uint16_t* B1g = g_w1t + ((size_t)head * FH + n0) * HD;
    const uint16_t* B3g = g_w3t + ((size_t)head * FH + n0) * HD;

    // loaders: rows are 64 fp16 = 128B = 8 chunks of 16B
    const int lrow = tid >> 3;          // 0..31
    const int lq   = tid & 7;           // chunk
    uint32_t adst[4], bdst[2];
    const uint16_t* asrc[4];
    const uint16_t* b1src[2];
    const uint16_t* b3src[2];
#pragma unroll
    for (int t = 0; t < 4; t++) {
        int r = lrow + 32 * t;          // 0..127
        adst[t] = (uint32_t)r * 128 + ((uint32_t)(lq ^ (r & 7)) << 4);
        asrc[t] = Ag + (size_t)r * HD + lq * 8;
    }
#pragma unroll
    for (int t = 0; t < 2; t++) {
        int r = lrow + 32 * t;          // 0..63
        bdst[t] = (uint32_t)r * 128 + ((uint32_t)(lq ^ (r & 7)) << 4);
        b1src[t] = B1g + (size_t)r * HD + lq * 8;
        b3src[t] = B3g + (size_t)r * HD + lq * 8;
    }

    // compute mapping (m16n8k16 fragments)
    const int lane = tid & 31, warp = tid >> 5;
    const int wm = warp & 1, wn = warp >> 1;        // 2 x 4
    uint32_t aoff[4], boff;
    {
        int rb = wm * 64 + (lane & 7) + 8 * ((lane >> 3) & 1);
        int c  = lane >> 4;             // k16-half chunk
#pragma unroll
        for (int mi = 0; mi < 4; mi++) {
            int m = rb + 16 * mi;
            aoff[mi] = (uint32_t)m * 128 + ((uint32_t)(c ^ (m & 7)) << 4);
        }
        int n = wn * 16 + (lane & 7) + 8 * ((lane >> 3) & 1);
        boff = (uint32_t)n * 128 + ((uint32_t)(c ^ (n & 7)) << 4);
    }

    float acc1[8][4], acc3[8][4];
#pragma unroll
    for (int i = 0; i < 8; i++)
#pragma unroll
        for (int j = 0; j < 4; j++) { acc1[i][j] = 0.f; acc3[i][j] = 0.f; }

    auto load_tile = [&](int kt, int buf) {
        uint32_t s = sbase + buf * 32768u;
#pragma unroll
        for (int t = 0; t < 4; t++) cp16(s + adst[t], asrc[t] + kt * 64);
#pragma unroll
        for (int t = 0; t < 2; t++) cp16(s + 16384u + bdst[t], b1src[t] + kt * 64);
#pragma unroll
        for (int t = 0; t < 2; t++) cp16(s + 24576u + bdst[t], b3src[t] + kt * 64);
    };

    load_tile(0, 0); cp_commit();
    load_tile(1, 1); cp_commit();

    for (int kt = 0; kt < KT; kt++) {
        if (kt == KT - 1) cp_wait<0>(); else cp_wait<1>();
        __syncthreads();
        if (kt + 2 < KT) { load_tile(kt + 2, (kt + 2) % 3); cp_commit(); }

        uint32_t sA  = sbase + (uint32_t)(kt % 3) * 32768u;
        uint32_t sB1 = sA + 16384u;
        uint32_t sB3 = sA + 24576u;
#pragma unroll
        for (int j = 0; j < 4; j++) {          // k16 steps within k64 tile
            uint32_t xo = (uint32_t)j << 5;
            uint32_t a[4][4], b1[4], b3[4];
#pragma unroll
            for (int mi = 0; mi < 4; mi++) ldsm4(a[mi], sA + (aoff[mi] ^ xo));
            ldsm4(b1, sB1 + (boff ^ xo));
            ldsm4(b3, sB3 + (boff ^ xo));
#pragma unroll
            for (int mi = 0; mi < 4; mi++)
#pragma unroll
                for (int nj = 0; nj < 2; nj++) {
                    mma16(acc1[mi * 2 + nj], a[mi], b1[nj], b1[nj + 2]);
                    mma16(acc3[mi * 2 + nj], a[mi], b3[nj], b3[nj + 2]);
                }
        }
    }

    // epilogue: fp16(silu(acc1)*acc3) -> g_gate (head-major [h][b][FH])
    const int g = lane >> 2, tg = lane & 3;
    uint16_t* c = g_gate + ((size_t)head * BATCH + b0) * FH + n0;
#pragma unroll
    for (int mi = 0; mi < 4; mi++) {
#pragma unroll
        for (int nj = 0; nj < 2; nj++) {
            float* d1 = acc1[mi * 2 + nj];
            float* d3 = acc3[mi * 2 + nj];
            int row = wm * 64 + mi * 16 + g;
            int col = wn * 16 + nj * 8 + 2 * tg;
#pragma unroll
            for (int h = 0; h < 2; h++) {
                float a0 = d1[2 * h], a1 = d1[2 * h + 1];
                float g0 = a0 / (1.f + __expf(-a0)) * d3[2 * h];
                float g1 = a1 / (1.f + __expf(-a1)) * d3[2 * h + 1];
                *(uint32_t*)(c + (size_t)(row + 8 * h) * FH + col) = f2h2(g0, g1);
            }
        }
    }
}

// ---------------- kernel 3: out = G @ W2 + P (token-major out) --------------
// fp16 path. CTA: 128x128, K=512, k-tile 64. warps 2(M) x 4(N); warp tile 64x32.
__global__ __launch_bounds__(256, 2) void ffn2_kernel(float* __restrict__ outp)
{
    constexpr int KT = FH / 64;   // 8
    extern __shared__ char smem[];
    const uint32_t sbase = smem_u32(smem);

    const int head = blockIdx.z;
    const int b0 = blockIdx.x * 128;
    const int n0 = blockIdx.y * 128;
    const int tid = threadIdx.x;

    const uint16_t* Ag = g_gate + ((size_t)head * BATCH + b0) * FH;
    const uint16_t* Bg = g_w2t  + ((size_t)head * HD + n0) * FH;

    const int lrow = tid >> 3;
    const int lq   = tid & 7;
    uint32_t adst[4];
    const uint16_t* asrc[4];
    const uint16_t* bsrc[4];
#pragma unroll
    for (int t = 0; t < 4; t++) {
        int r = lrow + 32 * t;          // 0..127 (A rows and B rows both 128)
        adst[t] = (uint32_t)r * 128 + ((uint32_t)(lq ^ (r & 7)) << 4);
        asrc[t] = Ag + (size_t)r * FH + lq * 8;
        bsrc[t] = Bg + (size_t)r * FH + lq * 8;
    }

    const int lane = tid & 31, warp = tid >> 5;
    const int wm = warp & 1, wn = warp >> 1;
    uint32_t aoff[4], boff[2];
    {
        int rb = wm * 64 + (lane & 7) + 8 * ((lane >> 3) & 1);
        int c  = lane >> 4;
#pragma unroll
        for (int mi = 0; mi < 4; mi++) {
            int m = rb + 16 * mi;
            aoff[mi] = (uint32_t)m * 128 + ((uint32_t)(c ^ (m & 7)) << 4);
        }
#pragma unroll
        for (int p = 0; p < 2; p++) {
            int n = wn * 32 + p * 16 + (lane & 7) + 8 * ((lane >> 3) & 1);
            boff[p] = (uint32_t)n * 128 + ((uint32_t)(c ^ (n & 7)) << 4);
        }
    }

    float acc[16][4];
#pragma unroll
    for (int i = 0; i < 16; i++)
#pragma unroll
        for (int j = 0; j < 4; j++) acc[i][j] = 0.f;

    auto load_tile = [&](int kt, int buf) {
        uint32_t s = sbase + buf * 32768u;
#pragma unroll
        for (int t = 0; t < 4; t++) cp16(s + adst[t], asrc[t] + kt * 64);
#pragma unroll
        for (int t = 0; t < 4; t++) cp16(s + 16384u + adst[t], bsrc[t] + kt * 64);
    };

    load_tile(0, 0); cp_commit();
    load_tile(1, 1); cp_commit();

    for (int kt = 0; kt < KT; kt++) {
        if (kt == KT - 1) cp_wait<0>(); else cp_wait<1>();
        __syncthreads();
        if (kt + 2 < KT) { load_tile(kt + 2, (kt + 2) % 3); cp_commit(); }

        uint32_t sA = sbase + (uint32_t)(kt % 3) * 32768u;
        uint32_t sB = sA + 16384u;
#pragma unroll
        for (int j = 0; j < 4; j++) {
            uint32_t xo = (uint32_t)j << 5;
            uint32_t a[4][4], b[2][4];
#pragma unroll
            for (int mi = 0; mi < 4; mi++) ldsm4(a[mi], sA + (aoff[mi] ^ xo));
#pragma unroll
            for (int p = 0; p < 2; p++) ldsm4(b[p], sB + (boff[p] ^ xo));
#pragma unroll
            for (int mi = 0; mi < 4; mi++)
#pragma unroll
                for (int nj = 0; nj < 4; nj++)
                    mma16(acc[mi * 4 + nj], a[mi],
                          b[nj >> 1][nj & 1], b[nj >> 1][(nj & 1) + 2]);
        }
    }

    const int g = lane >> 2, tg = lane & 3;
    const uint16_t* px = g_p + ((size_t)head * BATCH + b0) * HD + n0;
#pragma unroll
    for (int mi = 0; mi < 4; mi++) {
#pragma unroll
        for (int nj = 0; nj < 4; nj++) {
            float* d = acc[mi * 4 + nj];
            int row = wm * 64 + mi * 16 + g;
            int col = wn * 32 + nj * 8 + 2 * tg;
#pragma unroll
            for (int h = 0; h < 2; h++) {
                __half2 ph = *(const __half2*)(px + (size_t)(row + 8 * h) * HD + col);
                float2 pv = __half22float2(ph);
                float2 o = make_float2(d[2 * h] + pv.x, d[2 * h + 1] + pv.y);
                *(float2*)(outp + (size_t)(b0 + row + 8 * h) * NH * HD
                                + (size_t)head * HD + n0 + col) = o;
            }
        }
    }
}

// ---------------- launcher --------------------------------------------------
extern "C" void kernel_launch(void* const* d_in, const int* in_sizes, int n_in,
                              void* d_out, int out_size)
{
    const float* x    = (const float*)d_in[0];
    const float* n1w  = (const float*)d_in[1];
    const float* n2w  = (const float*)d_in[2];
    const float* w1   = (const float*)d_in[3];
    const float* w3   = (const float*)d_in[4];
    const float* w2   = (const float*)d_in[5];
    const float* mask = (const float*)d_in[6];
    float* out = (float*)d_out;

    cudaFuncSetAttribute(ffn1_kernel, cudaFuncAttributeMaxDynamicSharedMemorySize, 98304);
    cudaFuncSetAttribute(ffn2_kernel, cudaFuncAttributeMaxDynamicSharedMemorySize, 98304);

    transpose_kernel<<<dim3(16, 16, 48), 256>>>(w1, w3, w2);
    mix_kernel<<<BATCH, 512>>>(x, n1w, n2w, mask);
    ffn1_kernel<<<dim3(BATCH / 128, FH / 64, NH), 256, 98304>>>();
    ffn2_kernel<<<dim3(BATCH / 128, HD / 128, NH), 256, 98304>>>(out);
}